// round 1
// baseline (speedup 1.0000x reference)
#include <cuda_runtime.h>

#define KTAPS 27
#define C 32
#define NB 8
#define NPB 128           // nodes per block
#define NPW 16            // nodes per warp
#define GEPS 1e-5f

// ---- device-global stat accumulators (allocation-free scratch) ----
__device__ __align__(16) float g_sum[NB * C];
__device__ __align__(16) float g_sumsq[NB * C];
__device__ float g_cnt[NB];
__device__ __align__(16) float g_scale[NB * C];
__device__ __align__(16) float g_shift[NB * C];

// ---------------------------------------------------------------------------
__global__ void zero_stats_kernel() {
    int t = threadIdx.x;
    if (t < NB * C) { g_sum[t] = 0.f; g_sumsq[t] = 0.f; }
    if (t < NB) g_cnt[t] = 0.f;
}

// ---------------------------------------------------------------------------
// Pass 1: deconv + per-(batch,channel) sum / sumsq / count accumulation.
// Block: 256 threads = 8 warps; each warp owns 16 nodes, lane = output channel.
// Per k-tap, the block cooperatively stages the gathered 128x32 x-tile and the
// 32x32 W_k slice into double-buffered SMEM; LDG prefetch of tap k+1 overlaps
// compute of tap k. One __syncthreads per tap.
__global__ void __launch_bounds__(256, 2)
deconv_stats_kernel(const float* __restrict__ data,
                    const float* __restrict__ weights,
                    const int*   __restrict__ neigh,
                    const int*   __restrict__ batch_id,
                    float*       __restrict__ h_out,
                    int n_nodes)
{
    __shared__ float4 xs4[2 * NPB * (C / 4)];   // 2 x 128 x 8 float4 = 32 KB
    __shared__ float  wk_s[2 * C * C];          // 2 x 32 x 32        = 8 KB
    __shared__ int    batch_s[NPB];
    __shared__ float  sum_s[NB * C];
    __shared__ float  sq_s[NB * C];
    __shared__ float  cnt_s[NB];

    const int tid  = threadIdx.x;
    const int warp = tid >> 5;
    const int lane = tid & 31;
    const int base = blockIdx.x * NPB;
    const int nvalid = min(NPB, n_nodes - base);

    if (tid < NB * C) { sum_s[tid] = 0.f; sq_s[tid] = 0.f; }
    if (tid < NB) cnt_s[tid] = 0.f;
    if (tid < nvalid) batch_s[tid] = batch_id[base + tid];
    __syncthreads();
    if (tid < nvalid) atomicAdd(&cnt_s[batch_s[tid]], 1.0f);

    float acc[NPW];
#pragma unroll
    for (int m = 0; m < NPW; m++) acc[m] = 0.f;

    // per-thread staging assignment: 4 float4 slots per tap
    // slot fi in [0,1024): node = fi>>3, 16B segment = fi&7  -> coalesced LDG/STS
    float4 xr[4];
    float4 wr;
    {
#pragma unroll
        for (int j = 0; j < 4; j++) {
            int fi = tid + j * 256;
            int nl = fi >> 3, seg = fi & 7;
            float4 v = make_float4(0.f, 0.f, 0.f, 0.f);
            if (nl < nvalid) {
                int nb = neigh[(size_t)(base + nl) * KTAPS + 0];
                v = *reinterpret_cast<const float4*>(data + (size_t)nb * C + seg * 4);
            }
            xr[j] = v;
        }
        wr = *reinterpret_cast<const float4*>(weights + 0 * C * C + tid * 4);
    }

    int buf = 0;
    for (int k = 0; k < KTAPS; k++) {
        // commit staged tap k to SMEM
#pragma unroll
        for (int j = 0; j < 4; j++) {
            int fi = tid + j * 256;
            xs4[buf * 1024 + fi] = xr[j];
        }
        reinterpret_cast<float4*>(wk_s)[buf * 256 + tid] = wr;

        // prefetch tap k+1 (latency hidden under the barrier + compute below)
        if (k + 1 < KTAPS) {
            const int kn = k + 1;
#pragma unroll
            for (int j = 0; j < 4; j++) {
                int fi = tid + j * 256;
                int nl = fi >> 3, seg = fi & 7;
                float4 v = make_float4(0.f, 0.f, 0.f, 0.f);
                if (nl < nvalid) {
                    int nb = neigh[(size_t)(base + nl) * KTAPS + kn];
                    v = *reinterpret_cast<const float4*>(data + (size_t)nb * C + seg * 4);
                }
                xr[j] = v;
            }
            wr = *reinterpret_cast<const float4*>(weights + (size_t)kn * C * C + tid * 4);
        }
        __syncthreads();

        // W column for this lane (output channel)
        float w[C];
#pragma unroll
        for (int i = 0; i < C; i++)
            w[i] = wk_s[buf * 1024 + i * C + lane];

        const float4* xrow = &xs4[buf * 1024 + (warp * NPW) * 8];
#pragma unroll
        for (int m = 0; m < NPW; m++) {
#pragma unroll
            for (int s = 0; s < 8; s++) {
                float4 xv = xrow[m * 8 + s];   // LDS.128 broadcast
                acc[m] = fmaf(xv.x, w[s * 4 + 0], acc[m]);
                acc[m] = fmaf(xv.y, w[s * 4 + 1], acc[m]);
                acc[m] = fmaf(xv.z, w[s * 4 + 2], acc[m]);
                acc[m] = fmaf(xv.w, w[s * 4 + 3], acc[m]);
            }
        }
        buf ^= 1;
    }

    // epilogue: write h, accumulate segment stats (batch_id sorted -> ~1 flush)
    int curb = -1;
    float ls = 0.f, lq = 0.f;
#pragma unroll
    for (int m = 0; m < NPW; m++) {
        int nl = warp * NPW + m;
        if (nl < nvalid) {
            int n = base + nl;
            h_out[(size_t)n * C + lane] = acc[m];
            int b = batch_s[nl];
            if (b != curb) {
                if (curb >= 0) {
                    atomicAdd(&sum_s[curb * C + lane], ls);
                    atomicAdd(&sq_s[curb * C + lane], lq);
                }
                curb = b; ls = 0.f; lq = 0.f;
            }
            ls += acc[m];
            lq = fmaf(acc[m], acc[m], lq);
        }
    }
    if (curb >= 0) {
        atomicAdd(&sum_s[curb * C + lane], ls);
        atomicAdd(&sq_s[curb * C + lane], lq);
    }
    __syncthreads();
    if (tid < NB * C) {
        atomicAdd(&g_sum[tid], sum_s[tid]);
        atomicAdd(&g_sumsq[tid], sq_s[tid]);
    }
    if (tid < NB) atomicAdd(&g_cnt[tid], cnt_s[tid]);
}

// ---------------------------------------------------------------------------
// Pass 2: fold stats into per-(batch,channel) scale/shift.
// Matches reference: cnt = n_nodes*(C/G); inv_cnt = 1/(cnt+eps);
// mean_g over group channels; var via E-terms; inv_std = 1/sqrt(var+eps).
__global__ void stats_kernel(const float* __restrict__ gamma,
                             const float* __restrict__ beta)
{
    int t = threadIdx.x;              // exactly 256 = NB*C
    int b = t >> 5, c = t & 31, g = c >> 2;
    float cnt = g_cnt[b];
    float inv_cnt = 1.f / (cnt * 4.f + GEPS);   // C/G = 4
    float s = 0.f, q = 0.f;
#pragma unroll
    for (int j = 0; j < 4; j++) {
        s += g_sum[b * C + g * 4 + j];
        q += g_sumsq[b * C + g * 4 + j];
    }
    float mean = s * inv_cnt;
    // sum over group of (h-mean)^2 = q - 2*mean*s + (4*cnt)*mean^2
    float var = (q - 2.f * mean * s + 4.f * cnt * mean * mean) * inv_cnt;
    float inv_std = rsqrtf(var + GEPS);
    float ga = gamma[c] * inv_std;
    g_scale[t] = ga;
    g_shift[t] = beta[c] - mean * ga;
}

// ---------------------------------------------------------------------------
// Pass 3: in-place normalize + relu on d_out (h scratch).
__global__ void norm_relu_kernel(float* __restrict__ h,
                                 const int* __restrict__ batch_id,
                                 int n_nodes)
{
    int idx = blockIdx.x * blockDim.x + threadIdx.x;   // float4 index
    int total = n_nodes * (C / 4);
    if (idx >= total) return;
    int n = idx >> 3, s = idx & 7;
    int b = batch_id[n];
    float4 hv = reinterpret_cast<float4*>(h)[idx];
    float4 sc = reinterpret_cast<const float4*>(g_scale)[b * 8 + s];
    float4 sh = reinterpret_cast<const float4*>(g_shift)[b * 8 + s];
    float4 o;
    o.x = fmaxf(fmaf(hv.x, sc.x, sh.x), 0.f);
    o.y = fmaxf(fmaf(hv.y, sc.y, sh.y), 0.f);
    o.z = fmaxf(fmaf(hv.z, sc.z, sh.z), 0.f);
    o.w = fmaxf(fmaf(hv.w, sc.w, sh.w), 0.f);
    reinterpret_cast<float4*>(h)[idx] = o;
}

// ---------------------------------------------------------------------------
extern "C" void kernel_launch(void* const* d_in, const int* in_sizes, int n_in,
                              void* d_out, int out_size)
{
    const float* data     = (const float*)d_in[0];
    const float* weights  = (const float*)d_in[1];
    const float* gamma    = (const float*)d_in[2];
    const float* beta     = (const float*)d_in[3];
    const int*   neigh    = (const int*)d_in[4];
    const int*   batch_id = (const int*)d_in[5];
    float* out = (float*)d_out;

    const int n_nodes = in_sizes[0] / C;

    zero_stats_kernel<<<1, 512>>>();

    int grid1 = (n_nodes + NPB - 1) / NPB;
    deconv_stats_kernel<<<grid1, 256>>>(data, weights, neigh, batch_id, out, n_nodes);

    stats_kernel<<<1, NB * C>>>(gamma, beta);

    int total4 = n_nodes * (C / 4);
    int grid3 = (total4 + 255) / 256;
    norm_relu_kernel<<<grid3, 256>>>(out, batch_id, n_nodes);
}

// round 3
// speedup vs baseline: 2.1950x; 2.1950x over previous
#include <cuda_runtime.h>
#include <cstdint>

#define KTAPS 27
#define C 32
#define NB 8
#define TILE_M 256
#define THREADS 256
#define GEPS 1e-5f

// ---- dynamic SMEM layout ----
#define OFF_W   0                  // 27 * 4096 = 110592  (W^T tiles, swizzled tf32)
#define OFF_X   110592             // 2 * 256 * 128 = 65536 (X stages, swizzled tf32)
#define OFF_NG  176128             // 256 * 27 * 4 = 27648 (neighbor indices)
#define SMEM_TOTAL 203776

// ---- device-global stat accumulators ----
__device__ __align__(16) float g_sum[NB * C];
__device__ __align__(16) float g_sumsq[NB * C];
__device__ float g_cnt[NB];
__device__ __align__(16) float g_scale[NB * C];
__device__ __align__(16) float g_shift[NB * C];

// ===================== helpers =====================
__device__ __forceinline__ uint32_t smem_u32(const void* p) {
    uint32_t a;
    asm("{ .reg .u64 t; cvta.to.shared.u64 t, %1; cvt.u32.u64 %0, t; }"
        : "=r"(a) : "l"(p));
    return a;
}
__device__ __forceinline__ uint32_t f2tf32(float f) {
    uint32_t r; asm("cvt.rna.tf32.f32 %0, %1;" : "=r"(r) : "f"(f)); return r;
}
__device__ __forceinline__ uint32_t swz(uint32_t off) {
    return off ^ ((off >> 3) & 0x70);
}
__device__ __forceinline__ void ldsm4(uint32_t r[4], uint32_t addr) {
    asm volatile("ldmatrix.sync.aligned.m8n8.x4.shared.b16 {%0,%1,%2,%3}, [%4];"
        : "=r"(r[0]), "=r"(r[1]), "=r"(r[2]), "=r"(r[3]) : "r"(addr));
}
__device__ __forceinline__ void mma8(float c[4], const uint32_t a[4],
                                     uint32_t b0, uint32_t b1) {
    asm volatile("mma.sync.aligned.m16n8k8.row.col.f32.tf32.tf32.f32 "
        "{%0,%1,%2,%3}, {%4,%5,%6,%7}, {%8,%9}, {%0,%1,%2,%3};"
        : "+f"(c[0]), "+f"(c[1]), "+f"(c[2]), "+f"(c[3])
        : "r"(a[0]), "r"(a[1]), "r"(a[2]), "r"(a[3]), "r"(b0), "r"(b1));
}

// ===================== kernels =====================
__global__ void zero_stats_kernel() {
    int t = threadIdx.x;
    if (t < NB * C) { g_sum[t] = 0.f; g_sumsq[t] = 0.f; }
    if (t < NB) g_cnt[t] = 0.f;
}

// Persistent deconv: gather -> swizzled SMEM -> ldmatrix -> tf32 mma.sync.
// 8 warps, each computes 32 nodes x 32 out-channels; double-buffered X stage
// with register prefetch; all 27 W_k^T tiles staged once per CTA.
__global__ void __launch_bounds__(THREADS, 1)
deconv_kernel(const float* __restrict__ data,
              const float* __restrict__ weights,
              const int*   __restrict__ neigh,
              float*       __restrict__ h_out,
              int n_nodes, int n_tiles)
{
    extern __shared__ __align__(1024) char smem[];
    const uint32_t sb = smem_u32(smem);
    const int tid = threadIdx.x;
    const int warp = tid >> 5;
    const int lane = tid & 31;

    // Stage W^T: Wt[k][o][i] = weights[k][i][o], tf32-rounded, SW128 swizzled.
    for (int idx = tid; idx < KTAPS * 1024; idx += THREADS) {
        int k = idx >> 10, rem = idx & 1023;
        int i = rem >> 5, o = rem & 31;
        uint32_t v = f2tf32(weights[idx]);
        *(uint32_t*)(smem + OFF_W + k * 4096 + swz((uint32_t)(o * 128 + i * 4))) = v;
    }
    __syncthreads();

    // ldmatrix lane address patterns (tf32-as-b16 trick).
    const int lrow = (lane & 7) + ((lane >> 3) & 1) * 8;   // 0..15
    const int lhi  = (lane >> 4) * 16;                     // 0 or 16 bytes
    uint32_t a_swz[2], b_swz[2];
#pragma unroll
    for (int mb = 0; mb < 2; mb++)
        a_swz[mb] = swz((uint32_t)((warp * 32 + mb * 16 + lrow) * 128 + lhi));
#pragma unroll
    for (int nh = 0; nh < 2; nh++)
        b_swz[nh] = swz((uint32_t)((nh * 16 + lrow) * 128 + lhi));
    const uint32_t xb0 = sb + OFF_X;
    const uint32_t wb0 = sb + OFF_W;

    // producer slot pattern: thread handles 8 float4 slots, fixed seg.
    const int pseg = tid & 7;
    const int prow0 = tid >> 3;
    uint32_t psw[8];
#pragma unroll
    for (int j = 0; j < 8; j++)
        psw[j] = swz((uint32_t)((prow0 + j * 32) * 128 + pseg * 16));

#define LOAD_TAP(kk) do { \
    _Pragma("unroll") \
    for (int j = 0; j < 8; j++) { \
        int row = prow0 + j * 32; \
        float4 v = make_float4(0.f, 0.f, 0.f, 0.f); \
        if (row < nvalid) { \
            int nbi = *(const int*)(smem + OFF_NG + (row * KTAPS + (kk)) * 4); \
            v = *(const float4*)(data + (size_t)nbi * C + pseg * 4); \
        } \
        xr[j] = v; \
    } \
} while (0)

    int it = 0;
    for (int tile = blockIdx.x; tile < n_tiles; tile += gridDim.x) {
        const int base = tile * TILE_M;
        const int nvalid = min(TILE_M, n_nodes - base);

        // stage neighbor indices for this tile
        for (int idx = tid; idx < nvalid * KTAPS; idx += THREADS)
            *(int*)(smem + OFF_NG + idx * 4) = neigh[(size_t)base * KTAPS + idx];
        __syncthreads();

        float acc[2][4][4];
#pragma unroll
        for (int mb = 0; mb < 2; mb++)
#pragma unroll
            for (int nb = 0; nb < 4; nb++)
#pragma unroll
                for (int q = 0; q < 4; q++) acc[mb][nb][q] = 0.f;

        float4 xr[8];
        LOAD_TAP(0);

        for (int k = 0; k < KTAPS; k++) {
            const uint32_t bufoff = (uint32_t)(it & 1) * 32768u;
            char* xp = smem + OFF_X + bufoff;
            // commit tap k (tf32-round at store)
#pragma unroll
            for (int j = 0; j < 8; j++) {
                uint4 t;
                t.x = f2tf32(xr[j].x); t.y = f2tf32(xr[j].y);
                t.z = f2tf32(xr[j].z); t.w = f2tf32(xr[j].w);
                *(uint4*)(xp + psw[j]) = t;
            }
            if (k + 1 < KTAPS) LOAD_TAP(k + 1);
            __syncthreads();

            const uint32_t xstage = xb0 + bufoff;
            const uint32_t wbk = wb0 + (uint32_t)k * 4096u;
#pragma unroll
            for (int kb = 0; kb < 4; kb++) {
                const uint32_t kx = (uint32_t)(kb << 5);
                uint32_t a0[4], a1[4], q0[4], q1[4];
                ldsm4(a0, xstage + (a_swz[0] ^ kx));
                ldsm4(a1, xstage + (a_swz[1] ^ kx));
                ldsm4(q0, wbk + (b_swz[0] ^ kx));   // r0=nb0.b0 r1=nb1.b0 r2=nb0.b1 r3=nb1.b1
                ldsm4(q1, wbk + (b_swz[1] ^ kx));   // nb2/nb3
                mma8(acc[0][0], a0, q0[0], q0[2]);
                mma8(acc[0][1], a0, q0[1], q0[3]);
                mma8(acc[0][2], a0, q1[0], q1[2]);
                mma8(acc[0][3], a0, q1[1], q1[3]);
                mma8(acc[1][0], a1, q0[0], q0[2]);
                mma8(acc[1][1], a1, q0[1], q0[3]);
                mma8(acc[1][2], a1, q1[0], q1[2]);
                mma8(acc[1][3], a1, q1[1], q1[3]);
            }
            it++;
        }

        // epilogue: C-fragment -> h_out
#pragma unroll
        for (int mb = 0; mb < 2; mb++) {
            const int r0 = base + warp * 32 + mb * 16 + (lane >> 2);
            const int r1 = r0 + 8;
#pragma unroll
            for (int nb = 0; nb < 4; nb++) {
                const int cc = nb * 8 + 2 * (lane & 3);
                if (r0 < n_nodes)
                    *(float2*)(h_out + (size_t)r0 * C + cc) =
                        make_float2(acc[mb][nb][0], acc[mb][nb][1]);
                if (r1 < n_nodes)
                    *(float2*)(h_out + (size_t)r1 * C + cc) =
                        make_float2(acc[mb][nb][2], acc[mb][nb][3]);
            }
        }
        // next tile's neigh staging is ordered by the barrier at its start
    }
#undef LOAD_TAP
}

// Per-(batch,channel) sum/sumsq/count over h (batch_id sorted -> few flushes).
#define RNPB 256
__global__ void __launch_bounds__(256)
reduce_stats_kernel(const float* __restrict__ h,
                    const int* __restrict__ batch_id, int n_nodes)
{
    __shared__ float sum_s[NB * C], sq_s[NB * C], cnt_s[NB];
    __shared__ int batch_s[RNPB];
    const int tid = threadIdx.x, w = tid >> 5, c = tid & 31;
    const int base = blockIdx.x * RNPB;
    const int nvalid = min(RNPB, n_nodes - base);
    if (tid < NB * C) { sum_s[tid] = 0.f; sq_s[tid] = 0.f; }
    if (tid < NB) cnt_s[tid] = 0.f;
    if (tid < nvalid) batch_s[tid] = batch_id[base + tid];
    __syncthreads();
    if (tid < nvalid) atomicAdd(&cnt_s[batch_s[tid]], 1.0f);
    int curb = -1; float ls = 0.f, lq = 0.f;
#pragma unroll 4
    for (int m = 0; m < 32; m++) {
        int nl = w * 32 + m;
        if (nl < nvalid) {
            float v = h[(size_t)(base + nl) * C + c];
            int b = batch_s[nl];
            if (b != curb) {
                if (curb >= 0) { atomicAdd(&sum_s[curb * C + c], ls); atomicAdd(&sq_s[curb * C + c], lq); }
                curb = b; ls = 0.f; lq = 0.f;
            }
            ls += v; lq = fmaf(v, v, lq);
        }
    }
    if (curb >= 0) { atomicAdd(&sum_s[curb * C + c], ls); atomicAdd(&sq_s[curb * C + c], lq); }
    __syncthreads();
    if (tid < NB * C) { atomicAdd(&g_sum[tid], sum_s[tid]); atomicAdd(&g_sumsq[tid], sq_s[tid]); }
    if (tid < NB) atomicAdd(&g_cnt[tid], cnt_s[tid]);
}

__global__ void stats_kernel(const float* __restrict__ gamma,
                             const float* __restrict__ beta)
{
    int t = threadIdx.x;              // 256 = NB*C
    int b = t >> 5, c = t & 31, g = c >> 2;
    float cnt = g_cnt[b];
    float inv_cnt = 1.f / (cnt * 4.f + GEPS);   // C/G = 4
    float s = 0.f, q = 0.f;
#pragma unroll
    for (int j = 0; j < 4; j++) {
        s += g_sum[b * C + g * 4 + j];
        q += g_sumsq[b * C + g * 4 + j];
    }
    float mean = s * inv_cnt;
    float var = (q - 2.f * mean * s + 4.f * cnt * mean * mean) * inv_cnt;
    float inv_std = rsqrtf(var + GEPS);
    float ga = gamma[c] * inv_std;
    g_scale[t] = ga;
    g_shift[t] = beta[c] - mean * ga;
}

__global__ void norm_relu_kernel(float* __restrict__ h,
                                 const int* __restrict__ batch_id,
                                 int n_nodes)
{
    int idx = blockIdx.x * blockDim.x + threadIdx.x;
    int total = n_nodes * (C / 4);
    if (idx >= total) return;
    int n = idx >> 3, s = idx & 7;
    int b = batch_id[n];
    float4 hv = reinterpret_cast<float4*>(h)[idx];
    float4 sc = reinterpret_cast<const float4*>(g_scale)[b * 8 + s];
    float4 sh = reinterpret_cast<const float4*>(g_shift)[b * 8 + s];
    float4 o;
    o.x = fmaxf(fmaf(hv.x, sc.x, sh.x), 0.f);
    o.y = fmaxf(fmaf(hv.y, sc.y, sh.y), 0.f);
    o.z = fmaxf(fmaf(hv.z, sc.z, sh.z), 0.f);
    o.w = fmaxf(fmaf(hv.w, sc.w, sh.w), 0.f);
    reinterpret_cast<float4*>(h)[idx] = o;
}

// ===================== launch =====================
extern "C" void kernel_launch(void* const* d_in, const int* in_sizes, int n_in,
                              void* d_out, int out_size)
{
    const float* data     = (const float*)d_in[0];
    const float* weights  = (const float*)d_in[1];
    const float* gamma    = (const float*)d_in[2];
    const float* beta     = (const float*)d_in[3];
    const int*   neigh    = (const int*)d_in[4];
    const int*   batch_id = (const int*)d_in[5];
    float* out = (float*)d_out;

    const int n_nodes = in_sizes[0] / C;
    const int n_tiles = (n_nodes + TILE_M - 1) / TILE_M;

    cudaFuncSetAttribute(deconv_kernel,
                         cudaFuncAttributeMaxDynamicSharedMemorySize, SMEM_TOTAL);

    zero_stats_kernel<<<1, 512>>>();

    int grid = n_tiles < 148 ? n_tiles : 148;
    deconv_kernel<<<grid, THREADS, SMEM_TOTAL>>>(data, weights, neigh, out,
                                                 n_nodes, n_tiles);

    int gridR = (n_nodes + RNPB - 1) / RNPB;
    reduce_stats_kernel<<<gridR, 256>>>(out, batch_id, n_nodes);
    stats_kernel<<<1, NB * C>>>(gamma, beta);
    int total4 = n_nodes * (C / 4);
    norm_relu_kernel<<<(total4 + 255) / 256, 256>>>(out, batch_id, n_nodes);
}

// round 4
// speedup vs baseline: 2.6518x; 1.2081x over previous
#include <cuda_runtime.h>
#include <cstdint>

#define KTAPS 27
#define C 32
#define NB 8
#define TILE_M 256
#define THREADS 256
#define GEPS 1e-5f

// ---- dynamic SMEM layout ----
#define OFF_W   0                  // 27 * 4096 = 110592 (W^T tiles, swizzled tf32, K-permuted)
#define OFF_NG  110592             // 256 * 27 * 4 = 27648 (neighbor indices)
#define SMEM_TOTAL 138240

// ---- device-global stat accumulators ----
__device__ __align__(16) float g_sum[NB * C];
__device__ __align__(16) float g_sumsq[NB * C];
__device__ float g_cnt[NB];
__device__ __align__(16) float g_scale[NB * C];
__device__ __align__(16) float g_shift[NB * C];

// ===================== helpers =====================
__device__ __forceinline__ uint32_t smem_u32(const void* p) {
    uint32_t a;
    asm("{ .reg .u64 t; cvta.to.shared.u64 t, %1; cvt.u32.u64 %0, t; }"
        : "=r"(a) : "l"(p));
    return a;
}
__device__ __forceinline__ uint32_t f2tf32(float f) {
    uint32_t r; asm("cvt.rna.tf32.f32 %0, %1;" : "=r"(r) : "f"(f)); return r;
}
__device__ __forceinline__ uint32_t swz(uint32_t off) {
    return off ^ ((off >> 3) & 0x70);
}
__device__ __forceinline__ void ldsm4(uint32_t r[4], uint32_t addr) {
    asm volatile("ldmatrix.sync.aligned.m8n8.x4.shared.b16 {%0,%1,%2,%3}, [%4];"
        : "=r"(r[0]), "=r"(r[1]), "=r"(r[2]), "=r"(r[3]) : "r"(addr));
}
__device__ __forceinline__ void mma8(float c[4], const uint32_t a[4],
                                     uint32_t b0, uint32_t b1) {
    asm volatile("mma.sync.aligned.m16n8k8.row.col.f32.tf32.tf32.f32 "
        "{%0,%1,%2,%3}, {%4,%5,%6,%7}, {%8,%9}, {%0,%1,%2,%3};"
        : "+f"(c[0]), "+f"(c[1]), "+f"(c[2]), "+f"(c[3])
        : "r"(a[0]), "r"(a[1]), "r"(a[2]), "r"(a[3]), "r"(b0), "r"(b1));
}
// constant-index float4 component select (folds under full unroll)
#define COMP(v, j) ((j) == 0 ? (v).x : (j) == 1 ? (v).y : (j) == 2 ? (v).z : (v).w)

// ===================== kernels =====================
__global__ void zero_stats_kernel() {
    int t = threadIdx.x;
    if (t < NB * C) { g_sum[t] = 0.f; g_sumsq[t] = 0.f; }
    if (t < NB) g_cnt[t] = 0.f;
}

// Persistent deconv: A-fragments gathered DIRECTLY from GMEM (K-permuted so
// each lane does 2 coalesced LDG.128 per row), B via ldsm from K-permuted
// swizzled W tiles. No X stage, no barriers inside the tap loop.
__global__ void __launch_bounds__(THREADS, 1)
deconv_kernel(const float* __restrict__ data,
              const float* __restrict__ weights,
              const int*   __restrict__ neigh,
              float*       __restrict__ h_out,
              int n_nodes, int n_tiles)
{
    extern __shared__ __align__(1024) char smem[];
    const uint32_t sb = smem_u32(smem);
    const int tid = threadIdx.x;
    const int warp = tid >> 5;
    const int lane = tid & 31;
    const int q = lane & 3;            // quad column
    const int rbase = lane >> 2;       // row within 8-row group

    // Stage W^T with K-permutation: column kl(i) holds W[k][i][o] at row o.
    // phys i = 8q' + 4h + j  ->  kl = 8*((h<<1)|(j>>1)) + q' + 4*(j&1)
    for (int idx = tid; idx < KTAPS * 1024; idx += THREADS) {
        int k = idx >> 10, rem = idx & 1023;
        int i = rem >> 5, o = rem & 31;
        int qq = i >> 3, hh = (i >> 2) & 1, jj = i & 3;
        int kl = 8 * ((hh << 1) | (jj >> 1)) + qq + 4 * (jj & 1);
        uint32_t v = f2tf32(weights[idx]);
        *(uint32_t*)(smem + OFF_W + k * 4096 + swz((uint32_t)(o * 128 + kl * 4))) = v;
    }
    __syncthreads();

    // ldmatrix address pattern for B (validated tf32-as-b16 trick)
    const int lrow = (lane & 7) + ((lane >> 3) & 1) * 8;
    const int lhi  = (lane >> 4) * 16;
    uint32_t b_swz[2];
#pragma unroll
    for (int nh = 0; nh < 2; nh++)
        b_swz[nh] = swz((uint32_t)((nh * 16 + lrow) * 128 + lhi));
    const uint32_t wb0 = sb + OFF_W;

// load A-fragment raw data for tap kk into fA[buf]: [mb*4 + r01*2 + h]
#define LOAD_A(buf, kk) do { \
    _Pragma("unroll") \
    for (int mb = 0; mb < 2; mb++) { \
        int lr0 = warp * 32 + mb * 16 + rbase; \
        int nb0 = 0, nb1 = 0; \
        if (lr0 < nvalid)     nb0 = *(const int*)(smem + OFF_NG + (lr0 * KTAPS + (kk)) * 4); \
        if (lr0 + 8 < nvalid) nb1 = *(const int*)(smem + OFF_NG + ((lr0 + 8) * KTAPS + (kk)) * 4); \
        const float4* p0 = (const float4*)(data + (size_t)nb0 * C + q * 8); \
        const float4* p1 = (const float4*)(data + (size_t)nb1 * C + q * 8); \
        fA[buf][mb * 4 + 0] = p0[0]; \
        fA[buf][mb * 4 + 1] = p0[1]; \
        fA[buf][mb * 4 + 2] = p1[0]; \
        fA[buf][mb * 4 + 3] = p1[1]; \
    } \
} while (0)

    for (int tile = blockIdx.x; tile < n_tiles; tile += gridDim.x) {
        const int base = tile * TILE_M;
        const int nvalid = min(TILE_M, n_nodes - base);

        __syncthreads();   // previous tile's neigh readers done
        for (int idx = tid; idx < nvalid * KTAPS; idx += THREADS)
            *(int*)(smem + OFF_NG + idx * 4) = neigh[(size_t)base * KTAPS + idx];
        __syncthreads();

        float acc[2][4][4];
#pragma unroll
        for (int mb = 0; mb < 2; mb++)
#pragma unroll
            for (int nb = 0; nb < 4; nb++)
#pragma unroll
                for (int p = 0; p < 4; p++) acc[mb][nb][p] = 0.f;

        float4 fA[2][8];
        LOAD_A(0, 0);

#pragma unroll
        for (int k = 0; k < KTAPS; k++) {
            const int cur = k & 1;
            if (k + 1 < KTAPS) LOAD_A((k + 1) & 1, k + 1);

            const uint32_t wbk = wb0 + (uint32_t)k * 4096u;
#pragma unroll
            for (int kb = 0; kb < 4; kb++) {
                const uint32_t kx = (uint32_t)(kb << 5);
                uint32_t qf0[4], qf1[4];
                ldsm4(qf0, wbk + (b_swz[0] ^ kx));   // nb0/nb1 fragments
                ldsm4(qf1, wbk + (b_swz[1] ^ kx));   // nb2/nb3 fragments
                const int h  = kb >> 1;
                const int j0 = (kb & 1) * 2;
                const int j1 = j0 + 1;
#pragma unroll
                for (int mb = 0; mb < 2; mb++) {
                    uint32_t a[4];
                    a[0] = f2tf32(COMP(fA[cur][mb * 4 + 0 + h], j0));
                    a[1] = f2tf32(COMP(fA[cur][mb * 4 + 2 + h], j0));
                    a[2] = f2tf32(COMP(fA[cur][mb * 4 + 0 + h], j1));
                    a[3] = f2tf32(COMP(fA[cur][mb * 4 + 2 + h], j1));
                    mma8(acc[mb][0], a, qf0[0], qf0[2]);
                    mma8(acc[mb][1], a, qf0[1], qf0[3]);
                    mma8(acc[mb][2], a, qf1[0], qf1[2]);
                    mma8(acc[mb][3], a, qf1[1], qf1[3]);
                }
            }
        }

        // epilogue: C-fragment -> h_out
#pragma unroll
        for (int mb = 0; mb < 2; mb++) {
            const int r0 = base + warp * 32 + mb * 16 + (lane >> 2);
            const int r1 = r0 + 8;
#pragma unroll
            for (int nb = 0; nb < 4; nb++) {
                const int cc = nb * 8 + 2 * (lane & 3);
                if (r0 < n_nodes)
                    *(float2*)(h_out + (size_t)r0 * C + cc) =
                        make_float2(acc[mb][nb][0], acc[mb][nb][1]);
                if (r1 < n_nodes)
                    *(float2*)(h_out + (size_t)r1 * C + cc) =
                        make_float2(acc[mb][nb][2], acc[mb][nb][3]);
            }
        }
    }
#undef LOAD_A
}

// Per-(batch,channel) sum/sumsq/count over h (batch_id sorted -> few flushes).
#define RNPB 256
__global__ void __launch_bounds__(256)
reduce_stats_kernel(const float* __restrict__ h,
                    const int* __restrict__ batch_id, int n_nodes)
{
    __shared__ float sum_s[NB * C], sq_s[NB * C], cnt_s[NB];
    __shared__ int batch_s[RNPB];
    const int tid = threadIdx.x, w = tid >> 5, c = tid & 31;
    const int base = blockIdx.x * RNPB;
    const int nvalid = min(RNPB, n_nodes - base);
    if (tid < NB * C) { sum_s[tid] = 0.f; sq_s[tid] = 0.f; }
    if (tid < NB) cnt_s[tid] = 0.f;
    if (tid < nvalid) batch_s[tid] = batch_id[base + tid];
    __syncthreads();
    if (tid < nvalid) atomicAdd(&cnt_s[batch_s[tid]], 1.0f);
    int curb = -1; float ls = 0.f, lq = 0.f;
#pragma unroll 4
    for (int m = 0; m < 32; m++) {
        int nl = w * 32 + m;
        if (nl < nvalid) {
            float v = h[(size_t)(base + nl) * C + c];
            int b = batch_s[nl];
            if (b != curb) {
                if (curb >= 0) { atomicAdd(&sum_s[curb * C + c], ls); atomicAdd(&sq_s[curb * C + c], lq); }
                curb = b; ls = 0.f; lq = 0.f;
            }
            ls += v; lq = fmaf(v, v, lq);
        }
    }
    if (curb >= 0) { atomicAdd(&sum_s[curb * C + c], ls); atomicAdd(&sq_s[curb * C + c], lq); }
    __syncthreads();
    if (tid < NB * C) { atomicAdd(&g_sum[tid], sum_s[tid]); atomicAdd(&g_sumsq[tid], sq_s[tid]); }
    if (tid < NB) atomicAdd(&g_cnt[tid], cnt_s[tid]);
}

__global__ void stats_kernel(const float* __restrict__ gamma,
                             const float* __restrict__ beta)
{
    int t = threadIdx.x;              // 256 = NB*C
    int b = t >> 5, c = t & 31, g = c >> 2;
    float cnt = g_cnt[b];
    float inv_cnt = 1.f / (cnt * 4.f + GEPS);   // C/G = 4
    float s = 0.f, qq = 0.f;
#pragma unroll
    for (int j = 0; j < 4; j++) {
        s += g_sum[b * C + g * 4 + j];
        qq += g_sumsq[b * C + g * 4 + j];
    }
    float mean = s * inv_cnt;
    float var = (qq - 2.f * mean * s + 4.f * cnt * mean * mean) * inv_cnt;
    float inv_std = rsqrtf(var + GEPS);
    float ga = gamma[c] * inv_std;
    g_scale[t] = ga;
    g_shift[t] = beta[c] - mean * ga;
}

__global__ void norm_relu_kernel(float* __restrict__ h,
                                 const int* __restrict__ batch_id,
                                 int n_nodes)
{
    int idx = blockIdx.x * blockDim.x + threadIdx.x;
    int total = n_nodes * (C / 4);
    if (idx >= total) return;
    int n = idx >> 3, s = idx & 7;
    int b = batch_id[n];
    float4 hv = reinterpret_cast<float4*>(h)[idx];
    float4 sc = reinterpret_cast<const float4*>(g_scale)[b * 8 + s];
    float4 sh = reinterpret_cast<const float4*>(g_shift)[b * 8 + s];
    float4 o;
    o.x = fmaxf(fmaf(hv.x, sc.x, sh.x), 0.f);
    o.y = fmaxf(fmaf(hv.y, sc.y, sh.y), 0.f);
    o.z = fmaxf(fmaf(hv.z, sc.z, sh.z), 0.f);
    o.w = fmaxf(fmaf(hv.w, sc.w, sh.w), 0.f);
    reinterpret_cast<float4*>(h)[idx] = o;
}

// ===================== launch =====================
extern "C" void kernel_launch(void* const* d_in, const int* in_sizes, int n_in,
                              void* d_out, int out_size)
{
    const float* data     = (const float*)d_in[0];
    const float* weights  = (const float*)d_in[1];
    const float* gamma    = (const float*)d_in[2];
    const float* beta     = (const float*)d_in[3];
    const int*   neigh    = (const int*)d_in[4];
    const int*   batch_id = (const int*)d_in[5];
    float* out = (float*)d_out;

    const int n_nodes = in_sizes[0] / C;
    const int n_tiles = (n_nodes + TILE_M - 1) / TILE_M;

    cudaFuncSetAttribute(deconv_kernel,
                         cudaFuncAttributeMaxDynamicSharedMemorySize, SMEM_TOTAL);

    zero_stats_kernel<<<1, 512>>>();

    int grid = n_tiles < 148 ? n_tiles : 148;
    deconv_kernel<<<grid, THREADS, SMEM_TOTAL>>>(data, weights, neigh, out,
                                                 n_nodes, n_tiles);

    int gridR = (n_nodes + RNPB - 1) / RNPB;
    reduce_stats_kernel<<<gridR, 256>>>(out, batch_id, n_nodes);
    stats_kernel<<<1, NB * C>>>(gamma, beta);
    int total4 = n_nodes * (C / 4);
    norm_relu_kernel<<<(total4 + 255) / 256, 256>>>(out, batch_id, n_nodes);
}